// round 1
// baseline (speedup 1.0000x reference)
#include <cuda_runtime.h>

// Problem shape (fixed by setup_inputs): x: (B=4, S=4096, D=64) float32
// out: (B, S) float32
#define S_LEN 4096
#define D_DIM 64

// Scratch: per-(b,t) L1 norms. 4*4096 floats = 64 KB. Device global (no alloc).
__device__ float g_norms[4 * S_LEN];

// ---------------------------------------------------------------------------
// Kernel 1: norms[row] = sum_d |x[row, d]|   (row = b*S + t)
// One warp per row: each lane loads a float2 (64 floats / 32 lanes), abs+add,
// warp shfl tree reduction.
// ---------------------------------------------------------------------------
__global__ void norms_kernel(const float* __restrict__ x, int n_rows) {
    int gwarp = (blockIdx.x * blockDim.x + threadIdx.x) >> 5;
    int lane  = threadIdx.x & 31;
    if (gwarp >= n_rows) return;

    const float2 v = reinterpret_cast<const float2*>(x + (size_t)gwarp * D_DIM)[lane];
    float s = fabsf(v.x) + fabsf(v.y);
#pragma unroll
    for (int o = 16; o > 0; o >>= 1)
        s += __shfl_xor_sync(0xffffffffu, s, o);

    if (lane == 0) g_norms[gwarp] = s;
}

// ---------------------------------------------------------------------------
// Kernel 2: for each (b, t): find the largest j < t with
//             norms[b,j] < 0.7f * (norms[b,t] + 1e-8f)
//           answer = t - j (the minimal tau), or 0 if none.
//
// Block = 256 threads (8 warps). Each block owns 32 consecutive t values of
// one batch row; the full 4096-float norms row is staged in smem (16 KB).
// Each warp handles 4 t's; for each t, the warp scans backward 32 elements
// per step using ballot, stopping at the first chunk with a hit. The highest
// set lane in that chunk is the nearest previous crossing.
// ---------------------------------------------------------------------------
#define SCAN_WARPS 8
#define T_PER_WARP 4

__global__ void scan_kernel(float* __restrict__ out, int S) {
    __shared__ float sn[S_LEN];

    const int b   = blockIdx.y;
    const int tid = threadIdx.x;

    // Cooperative load of the full norms row into smem (float4 vectorized).
    const float4* src = reinterpret_cast<const float4*>(g_norms + (size_t)b * S);
#pragma unroll
    for (int i = 0; i < (S_LEN / 4) / (SCAN_WARPS * 32); i++) {
        reinterpret_cast<float4*>(sn)[tid + i * (SCAN_WARPS * 32)] =
            src[tid + i * (SCAN_WARPS * 32)];
    }
    __syncthreads();

    const int warp = tid >> 5;
    const int lane = tid & 31;
    const int tbase = blockIdx.x * (SCAN_WARPS * T_PER_WARP) + warp * T_PER_WARP;

#pragma unroll
    for (int i = 0; i < T_PER_WARP; i++) {
        const int t = tbase + i;
        const float thr = 0.7f * (sn[t] + 1e-8f);

        int ans = 0;
        // Scan backward in aligned-to-t chunks of 32: lane 31 reads jhi,
        // lane 0 reads jhi-31. First chunk (highest j) with a hit wins;
        // within it, the highest set lane is the largest j.
        for (int jhi = t - 1; jhi >= 0; jhi -= 32) {
            const int j = jhi - 31 + lane;
            const bool pred = (j >= 0) && (sn[j] < thr);
            const unsigned m = __ballot_sync(0xffffffffu, pred);
            if (m) {
                const int lane_hit = 31 - __clz(m);
                ans = t - (jhi - 31 + lane_hit);
                break;
            }
        }

        if (lane == 0) out[(size_t)b * S + t] = (float)ans;
    }
}

// ---------------------------------------------------------------------------
// Launch
// ---------------------------------------------------------------------------
extern "C" void kernel_launch(void* const* d_in, const int* in_sizes, int n_in,
                              void* d_out, int out_size) {
    const float* x = (const float*)d_in[0];
    float* out = (float*)d_out;

    const int n_rows = out_size;          // B * S = 16384
    const int B = n_rows / S_LEN;         // 4

    // Kernel 1: one warp per row, 256 threads/block -> 8 rows per block.
    {
        int rows_per_block = 256 / 32;
        int blocks = (n_rows + rows_per_block - 1) / rows_per_block;
        norms_kernel<<<blocks, 256>>>(x, n_rows);
    }

    // Kernel 2: 32 t's per block.
    {
        dim3 grid(S_LEN / (SCAN_WARPS * T_PER_WARP), B);
        scan_kernel<<<grid, SCAN_WARPS * 32>>>(out, S_LEN);
    }
}

// round 3
// speedup vs baseline: 2.5172x; 2.5172x over previous
#include <cuda_runtime.h>

// Problem shape (fixed by setup_inputs): x: (B=4, S=4096, D=64) float32
// out: (B, S) float32
#define S_LEN 4096
#define D_DIM 64
#define N_CHUNKS (S_LEN / 32)   // 128

// Scratch: per-(b,t) L1 norms. Device global (no alloc).
__device__ float g_norms[4 * S_LEN];

// ---------------------------------------------------------------------------
// Kernel 1: norms[row] = sum_d |x[row, d]|
// One warp per row: lane loads float2 (64 f32 / 32 lanes), shfl tree reduce.
// ---------------------------------------------------------------------------
__global__ void norms_kernel(const float* __restrict__ x, int n_rows) {
    int gwarp = (blockIdx.x * blockDim.x + threadIdx.x) >> 5;
    int lane  = threadIdx.x & 31;
    if (gwarp >= n_rows) return;

    const float2 v = reinterpret_cast<const float2*>(x + (size_t)gwarp * D_DIM)[lane];
    float s = fabsf(v.x) + fabsf(v.y);
#pragma unroll
    for (int o = 16; o > 0; o >>= 1)
        s += __shfl_xor_sync(0xffffffffu, s, o);

    if (lane == 0) g_norms[gwarp] = s;
}

// ---------------------------------------------------------------------------
// Kernel 2: for each (b, t): nearest j < t with norms[j] < 0.7*(norms[t]+eps);
// answer = t - j, else 0.
//
// Hierarchical ballot scan:
//   smem: full 4096-float norms row + 128 chunk minima (32-elem chunks).
//   Per t: (A) ballot the partial chunk [t&~31, t), (B) ballot chunk minima
//   backward 32-at-a-time (<=4 steps), (C) ballot inside the found chunk.
//   Worst case 6 ballots per query vs 128 for a flat scan.
//
// Block = 256 threads (8 warps), covers 128 consecutive t of one batch row.
// Grid = (32, 4) -> 128 blocks.
// ---------------------------------------------------------------------------
#define SCAN_WARPS 8
#define T_PER_WARP 16

__global__ void scan_kernel(float* __restrict__ out) {
    __shared__ float sn[S_LEN];
    __shared__ float cmin[N_CHUNKS];

    const int b    = blockIdx.y;
    const int tid  = threadIdx.x;
    const int warp = tid >> 5;
    const int lane = tid & 31;

    // Coalesced load of the full norms row into smem (float4).
    const float4* src = reinterpret_cast<const float4*>(g_norms + (size_t)b * S_LEN);
#pragma unroll
    for (int i = 0; i < (S_LEN / 4) / 256; i++) {
        reinterpret_cast<float4*>(sn)[tid + i * 256] = src[tid + i * 256];
    }
    __syncthreads();

    // Chunk minima: each warp reduces 16 chunks, LDS + shfl tree.
#pragma unroll
    for (int i = 0; i < N_CHUNKS / SCAN_WARPS; i++) {
        const int c = warp * (N_CHUNKS / SCAN_WARPS) + i;
        float m = sn[c * 32 + lane];
#pragma unroll
        for (int o = 16; o > 0; o >>= 1)
            m = fminf(m, __shfl_xor_sync(0xffffffffu, m, o));
        if (lane == 0) cmin[c] = m;
    }
    __syncthreads();

    const int tbase = blockIdx.x * (SCAN_WARPS * T_PER_WARP) + warp * T_PER_WARP;
    float my_ans = 0.0f;  // lane i (i < T_PER_WARP) holds the answer for t = tbase + i

#pragma unroll 1
    for (int i = 0; i < T_PER_WARP; i++) {
        const int t = tbase + i;
        const float thr = 0.7f * (sn[t] + 1e-8f);

        int ans = 0;  // warp-uniform after each phase (ballot results are uniform)

        // (A) partial chunk containing t-1
        const int cb = t & ~31;
        {
            const int j = cb + lane;
            const bool pred = (j < t) && (sn[j] < thr);
            const unsigned m = __ballot_sync(0xffffffffu, pred);
            if (m) ans = t - (cb + 31 - __clz(m));
        }

        // (B)+(C) full chunks below
        if (ans == 0 && cb > 0) {
            const int ct = cb >> 5;  // first full-chunk index to scan is ct-1
            int found_c = -1;
            for (int chi = ct - 1; chi >= 0; chi -= 32) {
                const int c = chi - 31 + lane;
                const bool pred = (c >= 0) && (cmin[c] < thr);
                const unsigned m = __ballot_sync(0xffffffffu, pred);
                if (m) { found_c = chi - __clz(m); break; }
            }
            if (found_c >= 0) {
                const int j = found_c * 32 + lane;
                const unsigned m = __ballot_sync(0xffffffffu, sn[j] < thr);
                ans = t - (found_c * 32 + 31 - __clz(m));
            }
        }

        if (lane == i) my_ans = (float)ans;
    }

    // Coalesced store: lane i -> t = tbase + i. ONLY the first T_PER_WARP
    // lanes hold valid answers (this was the R2 bug: storing 32 lanes
    // raced zeros into the neighboring warp's region).
    if (lane < T_PER_WARP)
        out[(size_t)b * S_LEN + tbase + lane] = my_ans;
}

// ---------------------------------------------------------------------------
// Launch
// ---------------------------------------------------------------------------
extern "C" void kernel_launch(void* const* d_in, const int* in_sizes, int n_in,
                              void* d_out, int out_size) {
    const float* x = (const float*)d_in[0];
    float* out = (float*)d_out;

    const int n_rows = out_size;          // B * S = 16384
    const int B = n_rows / S_LEN;         // 4

    // Kernel 1: one warp per row, 8 rows per 256-thread block.
    {
        int rows_per_block = 256 / 32;
        int blocks = (n_rows + rows_per_block - 1) / rows_per_block;
        norms_kernel<<<blocks, 256>>>(x, n_rows);
    }

    // Kernel 2: 128 t's per block, grid (32, B).
    {
        dim3 grid(S_LEN / (SCAN_WARPS * T_PER_WARP), B);
        scan_kernel<<<grid, SCAN_WARPS * 32>>>(out);
    }
}

// round 4
// speedup vs baseline: 4.2941x; 1.7059x over previous
#include <cuda_runtime.h>

// Problem shape (fixed by setup_inputs): x: (B=4, S=4096, D=64) float32
// out: (B, S) float32
#define S_LEN  4096
#define D_DIM  64
#define CH     8              // chunk size (elements)
#define NCH    (S_LEN / CH)   // 512 chunks per row
#define LEVELS 9              // 2^9 = 512, covers all chunks

// Scratch: per-(b,t) L1 norms. Device global (no alloc).
__device__ float g_norms[4 * S_LEN];

// ---------------------------------------------------------------------------
// Kernel 1: norms[row] = sum_d |x[row, d]|
// One warp per row: lane loads float2 (64 f32 / 32 lanes), shfl tree reduce.
// ---------------------------------------------------------------------------
__global__ void norms_kernel(const float* __restrict__ x, int n_rows) {
    int gwarp = (blockIdx.x * blockDim.x + threadIdx.x) >> 5;
    int lane  = threadIdx.x & 31;
    if (gwarp >= n_rows) return;

    const float2 v = reinterpret_cast<const float2*>(x + (size_t)gwarp * D_DIM)[lane];
    float s = fabsf(v.x) + fabsf(v.y);
#pragma unroll
    for (int o = 16; o > 0; o >>= 1)
        s += __shfl_xor_sync(0xffffffffu, s, o);

    if (lane == 0) g_norms[gwarp] = s;
}

// ---------------------------------------------------------------------------
// Kernel 2: thread-per-query nearest-crossing search.
// For each (b, t): nearest j < t with norms[j] < 0.7*(norms[t]+eps);
// answer = t - j, else 0.
//
// Per block: stage the 4096-float norms row + build a 9-level range-min
// sparse table over 8-element chunk minima (st[l][c] = min of chunks
// [c, c+2^l)). Per thread (one query t):
//   A) predicated scan of the partial chunk [t&~7, t)      (<=7 LDS, no branch)
//   B) binary descend over st to the minimal pos with all chunks [pos, ct)
//      clean; greedy descend is exact, so chunk pos-1 is dirty if pos>0
//   C) predicated scan of chunk pos-1                      (8 LDS, no branch)
//
// Block = 256 threads = 256 queries. Grid = (16, 4) = 64 blocks, one wave.
// ---------------------------------------------------------------------------
#define QPB 256

__global__ void scan_kernel(float* __restrict__ out) {
    __shared__ float sn[S_LEN];           // 16 KB norms row
    __shared__ float st[LEVELS][NCH];     // 18 KB sparse table

    const int b   = blockIdx.y;
    const int tid = threadIdx.x;

    // Coalesced float4 load of the norms row.
    const float4* src = reinterpret_cast<const float4*>(g_norms + (size_t)b * S_LEN);
#pragma unroll
    for (int i = 0; i < (S_LEN / 4) / QPB; i++)
        reinterpret_cast<float4*>(sn)[tid + i * QPB] = src[tid + i * QPB];
    __syncthreads();

    // Level 0: 8-element chunk minima (2 chunks per thread, float4 LDS).
#pragma unroll
    for (int i = 0; i < NCH / QPB; i++) {
        const int c = tid + i * QPB;
        const float4 a = reinterpret_cast<float4*>(sn)[c * 2];
        const float4 d = reinterpret_cast<float4*>(sn)[c * 2 + 1];
        st[0][c] = fminf(fminf(fminf(a.x, a.y), fminf(a.z, a.w)),
                         fminf(fminf(d.x, d.y), fminf(d.z, d.w)));
    }
    __syncthreads();

    // Levels 1..8: st[l][c] = min(st[l-1][c], st[l-1][c + 2^(l-1)]).
#pragma unroll
    for (int l = 1; l < LEVELS; l++) {
#pragma unroll
        for (int i = 0; i < NCH / QPB; i++) {
            const int c  = tid + i * QPB;
            const int c2 = c + (1 << (l - 1));
            float v = st[l - 1][c];
            if (c2 < NCH) v = fminf(v, st[l - 1][c2]);
            st[l][c] = v;
        }
        __syncthreads();
    }

    // ----- per-thread query -----
    const int t = blockIdx.x * QPB + tid;
    const float thr = 0.7f * (sn[t] + 1e-8f);

    // A) partial chunk [cb, t) — predicated, loads always in-bounds.
    const int cb = t & ~(CH - 1);
    int best = -1;
#pragma unroll
    for (int k = 0; k < CH; k++) {
        const int j = cb + k;
        if (j < t && sn[j] < thr) best = j;   // ascending k -> keeps max j
    }

    // B)+C) full chunks below.
    if (best < 0 && cb > 0) {
        int pos = cb >> 3;  // number of full chunks = t>>3, in [1, 511]
#pragma unroll
        for (int l = LEVELS - 1; l >= 0; l--) {
            const int npos = pos - (1 << l);
            const int idx  = npos >= 0 ? npos : 0;
            const float v  = st[l][idx];      // always-safe load, predicated use
            if (npos >= 0 && v >= thr) pos = npos;
        }
        if (pos > 0) {
            const int base = (pos - 1) * CH;
#pragma unroll
            for (int k = 0; k < CH; k++)
                if (sn[base + k] < thr) best = base + k;
        }
    }

    out[(size_t)b * S_LEN + t] = best >= 0 ? (float)(t - best) : 0.0f;
}

// ---------------------------------------------------------------------------
// Launch
// ---------------------------------------------------------------------------
extern "C" void kernel_launch(void* const* d_in, const int* in_sizes, int n_in,
                              void* d_out, int out_size) {
    const float* x = (const float*)d_in[0];
    float* out = (float*)d_out;

    const int n_rows = out_size;          // B * S = 16384
    const int B = n_rows / S_LEN;         // 4

    // Kernel 1: one warp per row, 8 rows per 256-thread block.
    {
        int rows_per_block = 256 / 32;
        int blocks = (n_rows + rows_per_block - 1) / rows_per_block;
        norms_kernel<<<blocks, 256>>>(x, n_rows);
    }

    // Kernel 2: 256 queries per block, grid (16, B).
    {
        dim3 grid(S_LEN / QPB, B);
        scan_kernel<<<grid, QPB>>>(out);
    }
}